// round 13
// baseline (speedup 1.0000x reference)
#include <cuda_runtime.h>
#include <cuda_bf16.h>
#include <math.h>
#include <stdint.h>

// Problem constants
#define B_  2
#define S_  2048
#define F_  1024
#define H_  16
#define D_  64
#define MTOK (B_*S_)     // 4096 tokens
#define HD   (H_*D_)     // 1024

// Device scratch (no cudaMalloc allowed)
__device__ float g_q[MTOK*HD];
__device__ float g_k[MTOK*HD];
__device__ float g_v[MTOK*HD];
__device__ float g_x[MTOK*HD];

// ===========================================================================
// Plain-TF32 machinery (PV) — proven.
// ===========================================================================
#define RP 20

__device__ __forceinline__ uint32_t f2tf(float x){
    uint32_t r; asm("cvt.rna.tf32.f32 %0, %1;" : "=r"(r) : "f"(x)); return r;
}
__device__ __forceinline__ void mma8(float* c, const uint32_t* a, const uint32_t* b){
    asm volatile("mma.sync.aligned.m16n8k8.row.col.f32.tf32.tf32.f32 "
        "{%0,%1,%2,%3}, {%4,%5,%6,%7}, {%8,%9}, {%0,%1,%2,%3};"
        : "+f"(c[0]),"+f"(c[1]),"+f"(c[2]),"+f"(c[3])
        : "r"(a[0]),"r"(a[1]),"r"(a[2]),"r"(a[3]), "r"(b[0]),"r"(b[1]));
}

template<int ROWS>   // row-major source [ROWS][ld], 16 k-cols
__device__ __forceinline__ void ldA_hi(uint32_t* Ah, const float* G, int ld){
    #pragma unroll
    for (int it = 0; it < ROWS/64; it++){
        int idx = threadIdx.x + it*256, row = idx >> 2, t = idx & 3;
        float4 v = *(const float4*)(G + (size_t)row*ld + 4*t);
        uint32_t* d = Ah + row*RP + t;
        d[0]=f2tf(v.x); d[4]=f2tf(v.y); d[8]=f2tf(v.z); d[12]=f2tf(v.w);
    }
}
template<int NC>     // transpose source: [16 k-rows][ld], NC n-cols
__device__ __forceinline__ void ldBt_hi(uint32_t* Bh, const float* G, int ld){
    #pragma unroll
    for (int it = 0; it < NC/64; it++){
        int idx = threadIdx.x + it*256;
        int kr = idx & 15, ng = idx >> 4;
        float4 v = *(const float4*)(G + (size_t)kr*ld + 4*ng);
        int p = (kr & 3)*4 + (kr >> 2);
        uint32_t* d = Bh + (4*ng)*RP + p;
        d[0]=f2tf(v.x); d[RP]=f2tf(v.y); d[2*RP]=f2tf(v.z); d[3*RP]=f2tf(v.w);
    }
}
__device__ __forceinline__ void fragA(uint32_t* a, const uint32_t* T, int row, int col){
    uint2 lo = *(const uint2*)(T + (size_t)row*RP + col);
    uint2 hi = *(const uint2*)(T + (size_t)(row+8)*RP + col);
    a[0]=lo.x; a[2]=lo.y; a[1]=hi.x; a[3]=hi.y;
}
__device__ __forceinline__ void fragB(uint32_t* b, const uint32_t* T, int row, int col){
    uint2 v = *(const uint2*)(T + (size_t)row*RP + col);
    b[0]=v.x; b[1]=v.y;
}
__device__ __forceinline__ void chunk_hi(float acc[2][4][4],
    const uint32_t* Ah, const uint32_t* Bh, int wm0, int wn0, int g, int c)
{
    #pragma unroll
    for (int s = 0; s < 2; s++){
        const int col = 4*c + 2*s;
        uint32_t ah[2][4], bh[4][2];
        #pragma unroll
        for (int mt = 0; mt < 2; mt++) fragA(ah[mt], Ah, wm0+mt*16+g, col);
        #pragma unroll
        for (int nt = 0; nt < 4; nt++) fragB(bh[nt], Bh, wn0+nt*8+g, col);
        #pragma unroll
        for (int mt = 0; mt < 2; mt++)
            #pragma unroll
            for (int nt = 0; nt < 4; nt++)
                mma8(acc[mt][nt], ah[mt], bh[nt]);
    }
}
#define PL_AH 0
#define PL_BH (128*RP)
#define PL_BUF (192*RP)      // words; 15360B per buf, x2 = 30720B

// ===========================================================================
// BF16 hi/lo split machinery with ldmatrix (all projections + scores).
// Row stride RB2=20 words (80B, 16B aligned) -> conflict-free ldmatrix.
// ===========================================================================
#define RB2 20

__device__ __forceinline__ void bsplit(float x, uint32_t& hb, uint32_t& lb){
    __nv_bfloat16 h = __float2bfloat16_rn(x);
    __nv_bfloat16 l = __float2bfloat16_rn(x - __bfloat162float(h));
    hb = (uint32_t)__bfloat16_as_ushort(h);
    lb = (uint32_t)__bfloat16_as_ushort(l);
}
__device__ __forceinline__ void mma16(float* c, const uint32_t* a, const uint32_t* b){
    asm volatile("mma.sync.aligned.m16n8k16.row.col.f32.bf16.bf16.f32 "
        "{%0,%1,%2,%3}, {%4,%5,%6,%7}, {%8,%9}, {%0,%1,%2,%3};"
        : "+f"(c[0]),"+f"(c[1]),"+f"(c[2]),"+f"(c[3])
        : "r"(a[0]),"r"(a[1]),"r"(a[2]),"r"(a[3]), "r"(b[0]),"r"(b[1]));
}
__device__ __forceinline__ void ldsm4(uint32_t* r, uint32_t a){
    asm volatile("ldmatrix.sync.aligned.m8n8.x4.shared.b16 {%0,%1,%2,%3}, [%4];"
        : "=r"(r[0]),"=r"(r[1]),"=r"(r[2]),"=r"(r[3]) : "r"(a));
}

template<int ROWS>
__device__ __forceinline__ void ldA_b2(uint32_t* Ah, uint32_t* Al, const float* G, int ld){
    #pragma unroll
    for (int it = 0; it < ROWS/32; it++){
        int idx = threadIdx.x + it*256;
        int row = idx >> 3, t = idx & 7;
        float4 v = *(const float4*)(G + (size_t)row*ld + 4*t);
        uint32_t hx,lx,hy,ly,hz,lz,hw,lw;
        bsplit(v.x,hx,lx); bsplit(v.y,hy,ly); bsplit(v.z,hz,lz); bsplit(v.w,hw,lw);
        uint2 hwd = make_uint2(hx | (hy<<16), hz | (hw<<16));
        uint2 lwd = make_uint2(lx | (ly<<16), lz | (lw<<16));
        *(uint2*)(Ah + (size_t)row*RB2 + 2*t) = hwd;
        *(uint2*)(Al + (size_t)row*RB2 + 2*t) = lwd;
    }
}
template<int NC>
__device__ __forceinline__ void ldBt_b2(uint32_t* Bh, uint32_t* Bl, const float* G, int ld){
    #pragma unroll
    for (int it = 0; it < NC/16; it++){
        int idx = threadIdx.x + it*256;
        int n = idx & (NC-1), wp = idx / NC;
        float a = G[(size_t)(2*wp)*ld + n];
        float b = G[(size_t)(2*wp+1)*ld + n];
        uint32_t ha,la,hb2,lb2;
        bsplit(a,ha,la); bsplit(b,hb2,lb2);
        Bh[(size_t)n*RB2 + wp] = ha | (hb2<<16);
        Bl[(size_t)n*RB2 + wp] = la | (lb2<<16);
    }
}

__device__ __forceinline__ void chunk_b2(float acc[2][4][4],
    uint32_t sAh, uint32_t sAl, uint32_t sBh, uint32_t sBl,
    int wm0, int wn0)
{
    const int L = threadIdx.x & 31;
    const int arow = (L & 7) + ((L >> 3) & 1) * 8;
    const int acol = (L >> 4) * 16;
    const int brow = (L & 7) + (L >> 4) * 8;
    const int bcol = ((L >> 3) & 1) * 16;

    #pragma unroll
    for (int s = 0; s < 2; s++){
        uint32_t ah[2][4], al[2][4], bbh[2][4], bbl[2][4];
        #pragma unroll
        for (int mt = 0; mt < 2; mt++){
            uint32_t off = (uint32_t)(wm0 + mt*16 + arow) * (RB2*4) + s*32 + acol;
            ldsm4(ah[mt], sAh + off);
            ldsm4(al[mt], sAl + off);
        }
        #pragma unroll
        for (int pr = 0; pr < 2; pr++){
            uint32_t off = (uint32_t)(wn0 + pr*16 + brow) * (RB2*4) + s*32 + bcol;
            ldsm4(bbh[pr], sBh + off);
            ldsm4(bbl[pr], sBl + off);
        }
        #pragma unroll
        for (int mt = 0; mt < 2; mt++)
            #pragma unroll
            for (int nt = 0; nt < 4; nt++){
                const uint32_t* bh_ = &bbh[nt>>1][(nt&1)*2];
                const uint32_t* bl_ = &bbl[nt>>1][(nt&1)*2];
                mma16(acc[mt][nt], al[mt], bh_);
                mma16(acc[mt][nt], ah[mt], bl_);
                mma16(acc[mt][nt], ah[mt], bh_);
            }
    }
}

#define B2_AH_B 0
#define B2_AL_B 10240        // 128*20*4
#define B2_BH_B 20480
#define B2_BL_B 25600        // + 64*20*4
#define B2_BUF_B 30720       // x2 buffers = 61440B

// ---------------------------------------------------------------------------
// Projection GEMM (bf16 split, all 4 projections):
// C[4096][1024] = alpha*(A @ W + bias).  Block 128m x 64n, warp tile 32x32,
// double-buffered k32 chunks.
// ---------------------------------------------------------------------------
__global__ __launch_bounds__(256, 2) void gemm_b2(
    const float* __restrict__ A, const float* __restrict__ W,
    const float* __restrict__ bias, float* __restrict__ C, float alpha)
{
    extern __shared__ __align__(16) uint32_t sm[];
    const uint32_t sbase = (uint32_t)__cvta_generic_to_shared(sm);
    const int tid = threadIdx.x, wid = tid >> 5, lane = tid & 31;
    const int g = lane >> 2, c = lane & 3;
    const int wm0 = (wid >> 1) * 32, wn0 = (wid & 1) * 32;
    const int m0 = blockIdx.y * 128, n0 = blockIdx.x * 64;

    float acc[2][4][4] = {};

    auto load = [&](int buf, int k0){
        uint32_t* bw = sm + buf * (B2_BUF_B/4);
        ldA_b2<128>(bw + B2_AH_B/4, bw + B2_AL_B/4, A + (size_t)m0*F_ + k0, F_);
        ldBt_b2<64>(bw + B2_BH_B/4, bw + B2_BL_B/4, W + (size_t)k0*F_ + n0, F_);
    };

    load(0, 0);
    __syncthreads();
    for (int ch = 0; ch < 32; ch++){
        const int cur = ch & 1;
        if (ch + 1 < 32) load(cur ^ 1, (ch + 1) * 32);
        uint32_t sb = sbase + cur * B2_BUF_B;
        chunk_b2(acc, sb + B2_AH_B, sb + B2_AL_B, sb + B2_BH_B, sb + B2_BL_B, wm0, wn0);
        __syncthreads();
    }

    #pragma unroll
    for (int mt = 0; mt < 2; mt++){
        int m = m0 + wm0 + mt*16 + g;
        #pragma unroll
        for (int nt = 0; nt < 4; nt++){
            int n = n0 + wn0 + nt*8 + 2*c;
            float b0v = bias[n], b1v = bias[n+1];
            *(float2*)&C[(size_t)m*F_ + n] =
                make_float2(alpha*(acc[mt][nt][0]+b0v), alpha*(acc[mt][nt][1]+b1v));
            *(float2*)&C[(size_t)(m+8)*F_ + n] =
                make_float2(alpha*(acc[mt][nt][2]+b0v), alpha*(acc[mt][nt][3]+b1v));
        }
    }
}

// ---------------------------------------------------------------------------
// Scores (bf16 split + ldmatrix): logits[q][k] = sum_d Q[q][d]*K[k][d].
// Block 128q x 64k, causal tiles only (early-exit above the diagonal).
// ---------------------------------------------------------------------------
__global__ __launch_bounds__(256, 2) void scores_b2(float* __restrict__ attn)
{
    const int kt2 = blockIdx.x;           // 64-wide k tile, 0..31
    const int qt  = blockIdx.y;           // 128-wide q tile, 0..15
    if (kt2 >= 2*(qt+1)) return;
    const int bh = blockIdx.z, b = bh >> 4, h = bh & 15;
    const float* Qb = g_q + ((size_t)b*S_*H_ + h)*D_;
    const float* Kb = g_k + ((size_t)b*S_*H_ + h)*D_;

    extern __shared__ __align__(16) uint32_t sm[];
    const uint32_t sbase = (uint32_t)__cvta_generic_to_shared(sm);
    const int tid = threadIdx.x, wid = tid >> 5, lane = tid & 31;
    const int g = lane >> 2, c = lane & 3;
    const int wm0 = (wid >> 1) * 32, wn0 = (wid & 1) * 32;
    const int q0 = qt * 128, k0 = kt2 * 64;

    float acc[2][4][4] = {};

    auto load = [&](int buf, int d0){
        uint32_t* bw = sm + buf * (B2_BUF_B/4);
        ldA_b2<128>(bw + B2_AH_B/4, bw + B2_AL_B/4, Qb + (size_t)q0*HD + d0, HD);
        ldA_b2<64> (bw + B2_BH_B/4, bw + B2_BL_B/4, Kb + (size_t)k0*HD + d0, HD);
    };

    load(0, 0);
    __syncthreads();
    for (int ch = 0; ch < 2; ch++){
        const int cur = ch & 1;
        if (ch + 1 < 2) load(cur ^ 1, (ch + 1) * 32);
        uint32_t sb = sbase + cur * B2_BUF_B;
        chunk_b2(acc, sb + B2_AH_B, sb + B2_AL_B, sb + B2_BH_B, sb + B2_BL_B, wm0, wn0);
        __syncthreads();
    }

    #pragma unroll
    for (int mt = 0; mt < 2; mt++){
        int q = q0 + wm0 + mt*16 + g;
        float* r0 = attn + ((size_t)bh*S_ + q)*S_;
        float* r1 = attn + ((size_t)bh*S_ + q + 8)*S_;
        #pragma unroll
        for (int nt = 0; nt < 4; nt++){
            int n = k0 + wn0 + nt*8 + 2*c;
            *(float2*)&r0[n] = make_float2(acc[mt][nt][0], acc[mt][nt][1]);
            *(float2*)&r1[n] = make_float2(acc[mt][nt][2], acc[mt][nt][3]);
        }
    }
}

// ---------------------------------------------------------------------------
// Causal softmax in-place. Reads ONLY the causal region (masked region is
// uninitialized and never loaded); writes the full row, masked -> exact 0.
// ---------------------------------------------------------------------------
__global__ __launch_bounds__(256) void softmax_kernel(float* __restrict__ attn)
{
    const int row = blockIdx.x;
    const int q = row % S_;
    float* p = attn + (size_t)row * S_;
    const int len = q + 1;
    const int tid = threadIdx.x;
    const int lane = tid & 31, warp = tid >> 5;

    __shared__ float sred[8];
    __shared__ float sbc[2];

    float4 v[2];
    float mx = -INFINITY;
    #pragma unroll
    for (int i = 0; i < 2; i++){
        int b0 = 4*(tid + i*256);
        float4 u = make_float4(-INFINITY, -INFINITY, -INFINITY, -INFINITY);
        if (b0 < len){
            u = *(const float4*)(p + b0);
            u.x = (b0+0 < len) ? u.x : -INFINITY;
            u.y = (b0+1 < len) ? u.y : -INFINITY;
            u.z = (b0+2 < len) ? u.z : -INFINITY;
            u.w = (b0+3 < len) ? u.w : -INFINITY;
        }
        v[i] = u;
        mx = fmaxf(mx, fmaxf(fmaxf(u.x, u.y), fmaxf(u.z, u.w)));
    }
    #pragma unroll
    for (int o = 16; o > 0; o >>= 1) mx = fmaxf(mx, __shfl_xor_sync(0xffffffffu, mx, o));
    if (lane == 0) sred[warp] = mx;
    __syncthreads();
    if (tid == 0){
        float m = sred[0];
        #pragma unroll
        for (int i = 1; i < 8; i++) m = fmaxf(m, sred[i]);
        sbc[0] = m;
    }
    __syncthreads();
    mx = sbc[0];

    float s = 0.f;
    #pragma unroll
    for (int i = 0; i < 2; i++){
        int b0 = 4*(tid + i*256);
        float4 u = v[i];
        if (b0 < len){
            u.x = (b0+0 < len) ? __expf(u.x - mx) : 0.f;
            u.y = (b0+1 < len) ? __expf(u.y - mx) : 0.f;
            u.z = (b0+2 < len) ? __expf(u.z - mx) : 0.f;
            u.w = (b0+3 < len) ? __expf(u.w - mx) : 0.f;
            s += (u.x + u.y) + (u.z + u.w);
        } else {
            u = make_float4(0.f, 0.f, 0.f, 0.f);
        }
        v[i] = u;
    }
    #pragma unroll
    for (int o = 16; o > 0; o >>= 1) s += __shfl_xor_sync(0xffffffffu, s, o);
    if (lane == 0) sred[warp] = s;
    __syncthreads();
    if (tid == 0){
        float t = 0.f;
        #pragma unroll
        for (int i = 0; i < 8; i++) t += sred[i];
        sbc[1] = t;
    }
    __syncthreads();
    const float inv = 1.0f / sbc[1];

    #pragma unroll
    for (int i = 0; i < 2; i++){
        int i4 = tid + i*256;
        float4 u = v[i];
        u.x *= inv; u.y *= inv; u.z *= inv; u.w *= inv;
        *(float4*)(p + 4*i4) = u;
    }
}

// ---------------------------------------------------------------------------
// PV (plain tf32): x[q][d] = sum_k P[q][k] * V[k][d].  Block 128q x 64d,
// triangle pairing (qt, 15-qt), double-buffered k16 chunks.
// ---------------------------------------------------------------------------
__device__ __forceinline__ void pv_tile(
    const float* __restrict__ attn, const float* __restrict__ Vb,
    float* __restrict__ Xb, int bh, int qt, uint32_t* sm)
{
    const int tid = threadIdx.x, wid = tid >> 5, lane = tid & 31;
    const int g = lane >> 2, c = lane & 3;
    const int wm0 = (wid >> 1) * 32, wn0 = (wid & 1) * 32;
    const int q0 = qt * 128;
    const int NCH = (qt + 1) * 8;

    float acc[2][4][4] = {};

    auto load = [&](int buf, int k0){
        uint32_t* b2 = sm + buf * PL_BUF;
        ldA_hi<128>(b2 + PL_AH, attn + ((size_t)bh*S_ + q0)*S_ + k0, S_);
        ldBt_hi<64>(b2 + PL_BH, Vb + (size_t)k0*HD, HD);
    };

    load(0, 0);
    __syncthreads();
    for (int ch = 0; ch < NCH; ch++){
        const int cur = ch & 1;
        if (ch + 1 < NCH) load(cur ^ 1, (ch + 1) * 16);
        uint32_t* b2 = sm + cur * PL_BUF;
        chunk_hi(acc, b2 + PL_AH, b2 + PL_BH, wm0, wn0, g, c);
        __syncthreads();
    }

    #pragma unroll
    for (int mt = 0; mt < 2; mt++){
        int q = q0 + wm0 + mt*16 + g;
        #pragma unroll
        for (int nt = 0; nt < 4; nt++){
            int n = wn0 + nt*8 + 2*c;
            *(float2*)&Xb[(size_t)q*HD + n] =
                make_float2(acc[mt][nt][0], acc[mt][nt][1]);
            *(float2*)&Xb[(size_t)(q+8)*HD + n] =
                make_float2(acc[mt][nt][2], acc[mt][nt][3]);
        }
    }
}

__global__ __launch_bounds__(256, 2) void pv_mma(const float* __restrict__ attn)
{
    extern __shared__ __align__(16) uint32_t sm[];
    const int pair = blockIdx.x;          // 0..7
    const int bh = blockIdx.y;
    const int b = bh >> 4, h = bh & 15;
    const float* Vb = g_v + ((size_t)b*S_*H_ + h)*D_;
    float* Xb = g_x + ((size_t)b*S_*H_ + h)*D_;

    pv_tile(attn, Vb, Xb, bh, pair, sm);
    __syncthreads();
    pv_tile(attn, Vb, Xb, bh, 15 - pair, sm);
}

// ---------------------------------------------------------------------------
// Launch
// ---------------------------------------------------------------------------
extern "C" void kernel_launch(void* const* d_in, const int* in_sizes, int n_in,
                              void* d_out, int out_size)
{
    const float* inputs_q  = (const float*)d_in[0];
    const float* inputs_kv = (const float*)d_in[1];
    // d_in[2] = mask (known causal, unused)
    const float* Wq = (const float*)d_in[3];
    const float* bq = (const float*)d_in[4];
    const float* Wk = (const float*)d_in[5];
    const float* bk = (const float*)d_in[6];
    const float* Wv = (const float*)d_in[7];
    const float* bv = (const float*)d_in[8];
    const float* Wo = (const float*)d_in[9];
    const float* bo = (const float*)d_in[10];

    float* out  = (float*)d_out;                       // [B,S,F]
    float* attn = out + (size_t)MTOK * F_;             // [B,H,S,S]

    float* gq; cudaGetSymbolAddress((void**)&gq, g_q);
    float* gk; cudaGetSymbolAddress((void**)&gk, g_k);
    float* gv; cudaGetSymbolAddress((void**)&gv, g_v);
    float* gx; cudaGetSymbolAddress((void**)&gx, g_x);

    const int SM_B2 = 2 * B2_BUF_B;     // 61440 bytes
    const int SM_PL = 2 * PL_BUF * 4;   // 30720 bytes
    cudaFuncSetAttribute(gemm_b2,   cudaFuncAttributeMaxDynamicSharedMemorySize, SM_B2);
    cudaFuncSetAttribute(scores_b2, cudaFuncAttributeMaxDynamicSharedMemorySize, SM_B2);
    cudaFuncSetAttribute(pv_mma,    cudaFuncAttributeMaxDynamicSharedMemorySize, SM_PL);

    dim3 gproj(F_ / 64, MTOK / 128);    // (16, 32)
    const float qscale = 0.125f;        // 1/sqrt(Dh)

    // All projections in bf16 hi/lo split (accuracy >= tf32, fewer MMA instrs).
    gemm_b2<<<gproj, 256, SM_B2>>>(inputs_q,  Wq, bq, gq, qscale);
    gemm_b2<<<gproj, 256, SM_B2>>>(inputs_kv, Wk, bk, gk, 1.0f);
    gemm_b2<<<gproj, 256, SM_B2>>>(inputs_kv, Wv, bv, gv, 1.0f);

    dim3 gsc(2 * S_ / 128, S_ / 128, B_ * H_);  // (32, 16, 32), causal early-exit
    scores_b2<<<gsc, 256, SM_B2>>>(attn);

    softmax_kernel<<<B_ * H_ * S_, 256>>>(attn);

    dim3 gpv(S_ / 256, B_ * H_);                // (8, 32) triangle pairs
    pv_mma<<<gpv, 256, SM_PL>>>(attn);

    gemm_b2<<<gproj, 256, SM_B2>>>(gx, Wo, bo, out, 1.0f);
}

// round 14
// speedup vs baseline: 1.3054x; 1.3054x over previous
#include <cuda_runtime.h>
#include <cuda_bf16.h>
#include <math.h>
#include <stdint.h>

// Problem constants
#define B_  2
#define S_  2048
#define F_  1024
#define H_  16
#define D_  64
#define MTOK (B_*S_)     // 4096 tokens
#define HD   (H_*D_)     // 1024

// Device scratch (no cudaMalloc allowed)
__device__ float g_q[MTOK*HD];
__device__ float g_k[MTOK*HD];
__device__ float g_v[MTOK*HD];
__device__ float g_x[MTOK*HD];

// ===========================================================================
// Plain-TF32 machinery (V-proj, out-proj, PV) — proven.
// ===========================================================================
#define RP 20

__device__ __forceinline__ uint32_t f2tf(float x){
    uint32_t r; asm("cvt.rna.tf32.f32 %0, %1;" : "=r"(r) : "f"(x)); return r;
}
__device__ __forceinline__ void mma8(float* c, const uint32_t* a, const uint32_t* b){
    asm volatile("mma.sync.aligned.m16n8k8.row.col.f32.tf32.tf32.f32 "
        "{%0,%1,%2,%3}, {%4,%5,%6,%7}, {%8,%9}, {%0,%1,%2,%3};"
        : "+f"(c[0]),"+f"(c[1]),"+f"(c[2]),"+f"(c[3])
        : "r"(a[0]),"r"(a[1]),"r"(a[2]),"r"(a[3]), "r"(b[0]),"r"(b[1]));
}

template<int ROWS>   // row-major source [ROWS][ld], 16 k-cols
__device__ __forceinline__ void ldA_hi(uint32_t* Ah, const float* G, int ld){
    #pragma unroll
    for (int it = 0; it < ROWS/64; it++){
        int idx = threadIdx.x + it*256, row = idx >> 2, t = idx & 3;
        float4 v = *(const float4*)(G + (size_t)row*ld + 4*t);
        uint32_t* d = Ah + row*RP + t;
        d[0]=f2tf(v.x); d[4]=f2tf(v.y); d[8]=f2tf(v.z); d[12]=f2tf(v.w);
    }
}
template<int NC>     // transpose source: [16 k-rows][ld], NC n-cols
__device__ __forceinline__ void ldBt_hi(uint32_t* Bh, const float* G, int ld){
    #pragma unroll
    for (int it = 0; it < NC/64; it++){
        int idx = threadIdx.x + it*256;
        int kr = idx & 15, ng = idx >> 4;
        float4 v = *(const float4*)(G + (size_t)kr*ld + 4*ng);
        int p = (kr & 3)*4 + (kr >> 2);
        uint32_t* d = Bh + (4*ng)*RP + p;
        d[0]=f2tf(v.x); d[RP]=f2tf(v.y); d[2*RP]=f2tf(v.z); d[3*RP]=f2tf(v.w);
    }
}
__device__ __forceinline__ void fragA(uint32_t* a, const uint32_t* T, int row, int col){
    uint2 lo = *(const uint2*)(T + (size_t)row*RP + col);
    uint2 hi = *(const uint2*)(T + (size_t)(row+8)*RP + col);
    a[0]=lo.x; a[2]=lo.y; a[1]=hi.x; a[3]=hi.y;
}
__device__ __forceinline__ void fragB(uint32_t* b, const uint32_t* T, int row, int col){
    uint2 v = *(const uint2*)(T + (size_t)row*RP + col);
    b[0]=v.x; b[1]=v.y;
}
__device__ __forceinline__ void chunk_hi(float acc[2][4][4],
    const uint32_t* Ah, const uint32_t* Bh, int wm0, int wn0, int g, int c)
{
    #pragma unroll
    for (int s = 0; s < 2; s++){
        const int col = 4*c + 2*s;
        uint32_t ah[2][4], bh[4][2];
        #pragma unroll
        for (int mt = 0; mt < 2; mt++) fragA(ah[mt], Ah, wm0+mt*16+g, col);
        #pragma unroll
        for (int nt = 0; nt < 4; nt++) fragB(bh[nt], Bh, wn0+nt*8+g, col);
        #pragma unroll
        for (int mt = 0; mt < 2; mt++)
            #pragma unroll
            for (int nt = 0; nt < 4; nt++)
                mma8(acc[mt][nt], ah[mt], bh[nt]);
    }
}
#define PL_AH 0
#define PL_BH (128*RP)
#define PL_BUF (192*RP)      // words; 15360B per buf, x2 = 30720B

// ===========================================================================
// BF16 hi/lo split machinery with ldmatrix (Q-proj, K-proj, scores).
// Row stride RB2=20 words (80B, 16B aligned) -> conflict-free ldmatrix.
// ===========================================================================
#define RB2 20

__device__ __forceinline__ void bsplit(float x, uint32_t& hb, uint32_t& lb){
    __nv_bfloat16 h = __float2bfloat16_rn(x);
    __nv_bfloat16 l = __float2bfloat16_rn(x - __bfloat162float(h));
    hb = (uint32_t)__bfloat16_as_ushort(h);
    lb = (uint32_t)__bfloat16_as_ushort(l);
}
__device__ __forceinline__ void mma16(float* c, const uint32_t* a, const uint32_t* b){
    asm volatile("mma.sync.aligned.m16n8k16.row.col.f32.bf16.bf16.f32 "
        "{%0,%1,%2,%3}, {%4,%5,%6,%7}, {%8,%9}, {%0,%1,%2,%3};"
        : "+f"(c[0]),"+f"(c[1]),"+f"(c[2]),"+f"(c[3])
        : "r"(a[0]),"r"(a[1]),"r"(a[2]),"r"(a[3]), "r"(b[0]),"r"(b[1]));
}
__device__ __forceinline__ void ldsm4(uint32_t* r, uint32_t a){
    asm volatile("ldmatrix.sync.aligned.m8n8.x4.shared.b16 {%0,%1,%2,%3}, [%4];"
        : "=r"(r[0]),"=r"(r[1]),"=r"(r[2]),"=r"(r[3]) : "r"(a));
}

template<int ROWS>
__device__ __forceinline__ void ldA_b2(uint32_t* Ah, uint32_t* Al, const float* G, int ld){
    #pragma unroll
    for (int it = 0; it < ROWS/32; it++){
        int idx = threadIdx.x + it*256;
        int row = idx >> 3, t = idx & 7;
        float4 v = *(const float4*)(G + (size_t)row*ld + 4*t);
        uint32_t hx,lx,hy,ly,hz,lz,hw,lw;
        bsplit(v.x,hx,lx); bsplit(v.y,hy,ly); bsplit(v.z,hz,lz); bsplit(v.w,hw,lw);
        uint2 hwd = make_uint2(hx | (hy<<16), hz | (hw<<16));
        uint2 lwd = make_uint2(lx | (ly<<16), lz | (lw<<16));
        *(uint2*)(Ah + (size_t)row*RB2 + 2*t) = hwd;
        *(uint2*)(Al + (size_t)row*RB2 + 2*t) = lwd;
    }
}
template<int NC>
__device__ __forceinline__ void ldBt_b2(uint32_t* Bh, uint32_t* Bl, const float* G, int ld){
    #pragma unroll
    for (int it = 0; it < NC/16; it++){
        int idx = threadIdx.x + it*256;
        int n = idx & (NC-1), wp = idx / NC;
        float a = G[(size_t)(2*wp)*ld + n];
        float b = G[(size_t)(2*wp+1)*ld + n];
        uint32_t ha,la,hb2,lb2;
        bsplit(a,ha,la); bsplit(b,hb2,lb2);
        Bh[(size_t)n*RB2 + wp] = ha | (hb2<<16);
        Bl[(size_t)n*RB2 + wp] = la | (lb2<<16);
    }
}

__device__ __forceinline__ void chunk_b2(float acc[2][4][4],
    uint32_t sAh, uint32_t sAl, uint32_t sBh, uint32_t sBl,
    int wm0, int wn0)
{
    const int L = threadIdx.x & 31;
    const int arow = (L & 7) + ((L >> 3) & 1) * 8;
    const int acol = (L >> 4) * 16;
    const int brow = (L & 7) + (L >> 4) * 8;
    const int bcol = ((L >> 3) & 1) * 16;

    #pragma unroll
    for (int s = 0; s < 2; s++){
        uint32_t ah[2][4], al[2][4], bbh[2][4], bbl[2][4];
        #pragma unroll
        for (int mt = 0; mt < 2; mt++){
            uint32_t off = (uint32_t)(wm0 + mt*16 + arow) * (RB2*4) + s*32 + acol;
            ldsm4(ah[mt], sAh + off);
            ldsm4(al[mt], sAl + off);
        }
        #pragma unroll
        for (int pr = 0; pr < 2; pr++){
            uint32_t off = (uint32_t)(wn0 + pr*16 + brow) * (RB2*4) + s*32 + bcol;
            ldsm4(bbh[pr], sBh + off);
            ldsm4(bbl[pr], sBl + off);
        }
        #pragma unroll
        for (int mt = 0; mt < 2; mt++)
            #pragma unroll
            for (int nt = 0; nt < 4; nt++){
                const uint32_t* bh_ = &bbh[nt>>1][(nt&1)*2];
                const uint32_t* bl_ = &bbl[nt>>1][(nt&1)*2];
                mma16(acc[mt][nt], al[mt], bh_);
                mma16(acc[mt][nt], ah[mt], bl_);
                mma16(acc[mt][nt], ah[mt], bh_);
            }
    }
}

#define B2_AH_B 0
#define B2_AL_B 10240        // 128*20*4
#define B2_BH_B 20480
#define B2_BL_B 25600        // + 64*20*4
#define B2_BUF_B 30720       // x2 buffers = 61440B

// ---------------------------------------------------------------------------
// Q/K projection (bf16 split): C = alpha*(A @ W + bias).  Block 128m x 64n,
// warp tile 32x32, double-buffered k32 chunks.
// ---------------------------------------------------------------------------
__global__ __launch_bounds__(256, 2) void gemm_b2(
    const float* __restrict__ A, const float* __restrict__ W,
    const float* __restrict__ bias, float* __restrict__ C, float alpha)
{
    extern __shared__ __align__(16) uint32_t sm[];
    const uint32_t sbase = (uint32_t)__cvta_generic_to_shared(sm);
    const int tid = threadIdx.x, wid = tid >> 5, lane = tid & 31;
    const int g = lane >> 2, c = lane & 3;
    const int wm0 = (wid >> 1) * 32, wn0 = (wid & 1) * 32;
    const int m0 = blockIdx.y * 128, n0 = blockIdx.x * 64;

    float acc[2][4][4] = {};

    auto load = [&](int buf, int k0){
        uint32_t* bw = sm + buf * (B2_BUF_B/4);
        ldA_b2<128>(bw + B2_AH_B/4, bw + B2_AL_B/4, A + (size_t)m0*F_ + k0, F_);
        ldBt_b2<64>(bw + B2_BH_B/4, bw + B2_BL_B/4, W + (size_t)k0*F_ + n0, F_);
    };

    load(0, 0);
    __syncthreads();
    for (int ch = 0; ch < 32; ch++){
        const int cur = ch & 1;
        if (ch + 1 < 32) load(cur ^ 1, (ch + 1) * 32);
        uint32_t sb = sbase + cur * B2_BUF_B;
        chunk_b2(acc, sb + B2_AH_B, sb + B2_AL_B, sb + B2_BH_B, sb + B2_BL_B, wm0, wn0);
        __syncthreads();
    }

    #pragma unroll
    for (int mt = 0; mt < 2; mt++){
        int m = m0 + wm0 + mt*16 + g;
        #pragma unroll
        for (int nt = 0; nt < 4; nt++){
            int n = n0 + wn0 + nt*8 + 2*c;
            float b0v = bias[n], b1v = bias[n+1];
            *(float2*)&C[(size_t)m*F_ + n] =
                make_float2(alpha*(acc[mt][nt][0]+b0v), alpha*(acc[mt][nt][1]+b1v));
            *(float2*)&C[(size_t)(m+8)*F_ + n] =
                make_float2(alpha*(acc[mt][nt][2]+b0v), alpha*(acc[mt][nt][3]+b1v));
        }
    }
}

// ---------------------------------------------------------------------------
// V / out projection (plain tf32): proven path.
// ---------------------------------------------------------------------------
__global__ __launch_bounds__(256, 2) void gemm_tf32(
    const float* __restrict__ A, const float* __restrict__ W,
    const float* __restrict__ bias, float* __restrict__ C, float alpha)
{
    extern __shared__ __align__(16) uint32_t sm[];
    const int tid = threadIdx.x, wid = tid >> 5, lane = tid & 31;
    const int g = lane >> 2, c = lane & 3;
    const int wm0 = (wid >> 1) * 32, wn0 = (wid & 1) * 32;
    const int m0 = blockIdx.y * 128, n0 = blockIdx.x * 64;

    float acc[2][4][4] = {};

    auto load = [&](int buf, int k0){
        uint32_t* b = sm + buf * PL_BUF;
        ldA_hi<128>(b + PL_AH, A + (size_t)m0*F_ + k0, F_);
        ldBt_hi<64>(b + PL_BH, W + (size_t)k0*F_ + n0, F_);
    };

    load(0, 0);
    __syncthreads();
    for (int ch = 0; ch < 64; ch++){
        const int cur = ch & 1;
        if (ch + 1 < 64) load(cur ^ 1, (ch + 1) * 16);
        uint32_t* b = sm + cur * PL_BUF;
        chunk_hi(acc, b + PL_AH, b + PL_BH, wm0, wn0, g, c);
        __syncthreads();
    }

    #pragma unroll
    for (int mt = 0; mt < 2; mt++){
        int m = m0 + wm0 + mt*16 + g;
        #pragma unroll
        for (int nt = 0; nt < 4; nt++){
            int n = n0 + wn0 + nt*8 + 2*c;
            float b0v = bias[n], b1v = bias[n+1];
            *(float2*)&C[(size_t)m*F_ + n] =
                make_float2(alpha*(acc[mt][nt][0]+b0v), alpha*(acc[mt][nt][1]+b1v));
            *(float2*)&C[(size_t)(m+8)*F_ + n] =
                make_float2(alpha*(acc[mt][nt][2]+b0v), alpha*(acc[mt][nt][3]+b1v));
        }
    }
}

// ---------------------------------------------------------------------------
// Scores (bf16 split + ldmatrix): logits[q][k] = sum_d Q[q][d]*K[k][d].
// Block 128q x 64k, causal tiles only (early-exit above the diagonal).
// ---------------------------------------------------------------------------
__global__ __launch_bounds__(256, 2) void scores_b2(float* __restrict__ attn)
{
    const int kt2 = blockIdx.x;           // 64-wide k tile, 0..31
    const int qt  = blockIdx.y;           // 128-wide q tile, 0..15
    if (kt2 >= 2*(qt+1)) return;
    const int bh = blockIdx.z, b = bh >> 4, h = bh & 15;
    const float* Qb = g_q + ((size_t)b*S_*H_ + h)*D_;
    const float* Kb = g_k + ((size_t)b*S_*H_ + h)*D_;

    extern __shared__ __align__(16) uint32_t sm[];
    const uint32_t sbase = (uint32_t)__cvta_generic_to_shared(sm);
    const int tid = threadIdx.x, wid = tid >> 5, lane = tid & 31;
    const int g = lane >> 2, c = lane & 3;
    const int wm0 = (wid >> 1) * 32, wn0 = (wid & 1) * 32;
    const int q0 = qt * 128, k0 = kt2 * 64;

    float acc[2][4][4] = {};

    auto load = [&](int buf, int d0){
        uint32_t* bw = sm + buf * (B2_BUF_B/4);
        ldA_b2<128>(bw + B2_AH_B/4, bw + B2_AL_B/4, Qb + (size_t)q0*HD + d0, HD);
        ldA_b2<64> (bw + B2_BH_B/4, bw + B2_BL_B/4, Kb + (size_t)k0*HD + d0, HD);
    };

    load(0, 0);
    __syncthreads();
    for (int ch = 0; ch < 2; ch++){
        const int cur = ch & 1;
        if (ch + 1 < 2) load(cur ^ 1, (ch + 1) * 32);
        uint32_t sb = sbase + cur * B2_BUF_B;
        chunk_b2(acc, sb + B2_AH_B, sb + B2_AL_B, sb + B2_BH_B, sb + B2_BL_B, wm0, wn0);
        __syncthreads();
    }

    #pragma unroll
    for (int mt = 0; mt < 2; mt++){
        int q = q0 + wm0 + mt*16 + g;
        float* r0 = attn + ((size_t)bh*S_ + q)*S_;
        float* r1 = attn + ((size_t)bh*S_ + q + 8)*S_;
        #pragma unroll
        for (int nt = 0; nt < 4; nt++){
            int n = k0 + wn0 + nt*8 + 2*c;
            *(float2*)&r0[n] = make_float2(acc[mt][nt][0], acc[mt][nt][1]);
            *(float2*)&r1[n] = make_float2(acc[mt][nt][2], acc[mt][nt][3]);
        }
    }
}

// ---------------------------------------------------------------------------
// Causal softmax in-place. Reads ONLY the causal region; writes full row,
// masked entries -> exact 0.
// ---------------------------------------------------------------------------
__global__ __launch_bounds__(256) void softmax_kernel(float* __restrict__ attn)
{
    const int row = blockIdx.x;
    const int q = row % S_;
    float* p = attn + (size_t)row * S_;
    const int len = q + 1;
    const int tid = threadIdx.x;
    const int lane = tid & 31, warp = tid >> 5;

    __shared__ float sred[8];
    __shared__ float sbc[2];

    float4 v[2];
    float mx = -INFINITY;
    #pragma unroll
    for (int i = 0; i < 2; i++){
        int b0 = 4*(tid + i*256);
        float4 u = make_float4(-INFINITY, -INFINITY, -INFINITY, -INFINITY);
        if (b0 < len){
            u = *(const float4*)(p + b0);
            u.x = (b0+0 < len) ? u.x : -INFINITY;
            u.y = (b0+1 < len) ? u.y : -INFINITY;
            u.z = (b0+2 < len) ? u.z : -INFINITY;
            u.w = (b0+3 < len) ? u.w : -INFINITY;
        }
        v[i] = u;
        mx = fmaxf(mx, fmaxf(fmaxf(u.x, u.y), fmaxf(u.z, u.w)));
    }
    #pragma unroll
    for (int o = 16; o > 0; o >>= 1) mx = fmaxf(mx, __shfl_xor_sync(0xffffffffu, mx, o));
    if (lane == 0) sred[warp] = mx;
    __syncthreads();
    if (tid == 0){
        float m = sred[0];
        #pragma unroll
        for (int i = 1; i < 8; i++) m = fmaxf(m, sred[i]);
        sbc[0] = m;
    }
    __syncthreads();
    mx = sbc[0];

    float s = 0.f;
    #pragma unroll
    for (int i = 0; i < 2; i++){
        int b0 = 4*(tid + i*256);
        float4 u = v[i];
        if (b0 < len){
            u.x = (b0+0 < len) ? __expf(u.x - mx) : 0.f;
            u.y = (b0+1 < len) ? __expf(u.y - mx) : 0.f;
            u.z = (b0+2 < len) ? __expf(u.z - mx) : 0.f;
            u.w = (b0+3 < len) ? __expf(u.w - mx) : 0.f;
            s += (u.x + u.y) + (u.z + u.w);
        } else {
            u = make_float4(0.f, 0.f, 0.f, 0.f);
        }
        v[i] = u;
    }
    #pragma unroll
    for (int o = 16; o > 0; o >>= 1) s += __shfl_xor_sync(0xffffffffu, s, o);
    if (lane == 0) sred[warp] = s;
    __syncthreads();
    if (tid == 0){
        float t = 0.f;
        #pragma unroll
        for (int i = 0; i < 8; i++) t += sred[i];
        sbc[1] = t;
    }
    __syncthreads();
    const float inv = 1.0f / sbc[1];

    #pragma unroll
    for (int i = 0; i < 2; i++){
        int i4 = tid + i*256;
        float4 u = v[i];
        u.x *= inv; u.y *= inv; u.z *= inv; u.w *= inv;
        *(float4*)(p + 4*i4) = u;
    }
}

// ---------------------------------------------------------------------------
// PV (plain tf32): x[q][d] = sum_k P[q][k] * V[k][d].  Block 128q x 64d,
// triangle pairing (qt, 15-qt), double-buffered k16 chunks.
// ---------------------------------------------------------------------------
__device__ __forceinline__ void pv_tile(
    const float* __restrict__ attn, const float* __restrict__ Vb,
    float* __restrict__ Xb, int bh, int qt, uint32_t* sm)
{
    const int tid = threadIdx.x, wid = tid >> 5, lane = tid & 31;
    const int g = lane >> 2, c = lane & 3;
    const int wm0 = (wid >> 1) * 32, wn0 = (wid & 1) * 32;
    const int q0 = qt * 128;
    const int NCH = (qt + 1) * 8;

    float acc[2][4][4] = {};

    auto load = [&](int buf, int k0){
        uint32_t* b2 = sm + buf * PL_BUF;
        ldA_hi<128>(b2 + PL_AH, attn + ((size_t)bh*S_ + q0)*S_ + k0, S_);
        ldBt_hi<64>(b2 + PL_BH, Vb + (size_t)k0*HD, HD);
    };

    load(0, 0);
    __syncthreads();
    for (int ch = 0; ch < NCH; ch++){
        const int cur = ch & 1;
        if (ch + 1 < NCH) load(cur ^ 1, (ch + 1) * 16);
        uint32_t* b2 = sm + cur * PL_BUF;
        chunk_hi(acc, b2 + PL_AH, b2 + PL_BH, wm0, wn0, g, c);
        __syncthreads();
    }

    #pragma unroll
    for (int mt = 0; mt < 2; mt++){
        int q = q0 + wm0 + mt*16 + g;
        #pragma unroll
        for (int nt = 0; nt < 4; nt++){
            int n = wn0 + nt*8 + 2*c;
            *(float2*)&Xb[(size_t)q*HD + n] =
                make_float2(acc[mt][nt][0], acc[mt][nt][1]);
            *(float2*)&Xb[(size_t)(q+8)*HD + n] =
                make_float2(acc[mt][nt][2], acc[mt][nt][3]);
        }
    }
}

__global__ __launch_bounds__(256, 2) void pv_mma(const float* __restrict__ attn)
{
    extern __shared__ __align__(16) uint32_t sm[];
    const int pair = blockIdx.x;          // 0..7
    const int bh = blockIdx.y;
    const int b = bh >> 4, h = bh & 15;
    const float* Vb = g_v + ((size_t)b*S_*H_ + h)*D_;
    float* Xb = g_x + ((size_t)b*S_*H_ + h)*D_;

    pv_tile(attn, Vb, Xb, bh, pair, sm);
    __syncthreads();
    pv_tile(attn, Vb, Xb, bh, 15 - pair, sm);
}

// ---------------------------------------------------------------------------
// Launch
// ---------------------------------------------------------------------------
extern "C" void kernel_launch(void* const* d_in, const int* in_sizes, int n_in,
                              void* d_out, int out_size)
{
    const float* inputs_q  = (const float*)d_in[0];
    const float* inputs_kv = (const float*)d_in[1];
    // d_in[2] = mask (known causal, unused)
    const float* Wq = (const float*)d_in[3];
    const float* bq = (const float*)d_in[4];
    const float* Wk = (const float*)d_in[5];
    const float* bk = (const float*)d_in[6];
    const float* Wv = (const float*)d_in[7];
    const float* bv = (const float*)d_in[8];
    const float* Wo = (const float*)d_in[9];
    const float* bo = (const float*)d_in[10];

    float* out  = (float*)d_out;                       // [B,S,F]
    float* attn = out + (size_t)MTOK * F_;             // [B,H,S,S]

    float* gq; cudaGetSymbolAddress((void**)&gq, g_q);
    float* gk; cudaGetSymbolAddress((void**)&gk, g_k);
    float* gv; cudaGetSymbolAddress((void**)&gv, g_v);
    float* gx; cudaGetSymbolAddress((void**)&gx, g_x);

    const int SM_B2 = 2 * B2_BUF_B;     // 61440 bytes
    const int SM_PL = 2 * PL_BUF * 4;   // 30720 bytes
    cudaFuncSetAttribute(gemm_b2,   cudaFuncAttributeMaxDynamicSharedMemorySize, SM_B2);
    cudaFuncSetAttribute(scores_b2, cudaFuncAttributeMaxDynamicSharedMemorySize, SM_B2);
    cudaFuncSetAttribute(gemm_tf32, cudaFuncAttributeMaxDynamicSharedMemorySize, SM_PL);
    cudaFuncSetAttribute(pv_mma,    cudaFuncAttributeMaxDynamicSharedMemorySize, SM_PL);

    dim3 gproj(F_ / 64, MTOK / 128);    // (16, 32)
    const float qscale = 0.125f;        // 1/sqrt(Dh)

    // Q/K projections in bf16 hi/lo split (protect softmax logits); V plain tf32.
    gemm_b2<<<gproj, 256, SM_B2>>>(inputs_q,  Wq, bq, gq, qscale);
    gemm_b2<<<gproj, 256, SM_B2>>>(inputs_kv, Wk, bk, gk, 1.0f);
    gemm_tf32<<<gproj, 256, SM_PL>>>(inputs_kv, Wv, bv, gv, 1.0f);

    dim3 gsc(2 * S_ / 128, S_ / 128, B_ * H_);  // (32, 16, 32), causal early-exit
    scores_b2<<<gsc, 256, SM_B2>>>(attn);

    softmax_kernel<<<B_ * H_ * S_, 256>>>(attn);

    dim3 gpv(S_ / 256, B_ * H_);                // (8, 32) triangle pairs
    pv_mma<<<gpv, 256, SM_PL>>>(attn);

    gemm_tf32<<<gproj, 256, SM_PL>>>(gx, Wo, bo, out, 1.0f);
}

// round 15
// speedup vs baseline: 1.3763x; 1.0544x over previous
#include <cuda_runtime.h>
#include <cuda_bf16.h>
#include <math.h>
#include <stdint.h>

// Problem constants
#define B_  2
#define S_  2048
#define F_  1024
#define H_  16
#define D_  64
#define MTOK (B_*S_)     // 4096 tokens
#define HD   (H_*D_)     // 1024

// Device scratch (no cudaMalloc allowed)
__device__ float g_q[MTOK*HD];
__device__ float g_k[MTOK*HD];
__device__ float g_v[MTOK*HD];
__device__ float g_x[MTOK*HD];

// ===========================================================================
// Plain-TF32 machinery (V-proj, out-proj) — proven.
// ===========================================================================
#define RP 20

__device__ __forceinline__ uint32_t f2tf(float x){
    uint32_t r; asm("cvt.rna.tf32.f32 %0, %1;" : "=r"(r) : "f"(x)); return r;
}
__device__ __forceinline__ void mma8(float* c, const uint32_t* a, const uint32_t* b){
    asm volatile("mma.sync.aligned.m16n8k8.row.col.f32.tf32.tf32.f32 "
        "{%0,%1,%2,%3}, {%4,%5,%6,%7}, {%8,%9}, {%0,%1,%2,%3};"
        : "+f"(c[0]),"+f"(c[1]),"+f"(c[2]),"+f"(c[3])
        : "r"(a[0]),"r"(a[1]),"r"(a[2]),"r"(a[3]), "r"(b[0]),"r"(b[1]));
}

template<int ROWS>   // row-major source [ROWS][ld], 16 k-cols
__device__ __forceinline__ void ldA_hi(uint32_t* Ah, const float* G, int ld){
    #pragma unroll
    for (int it = 0; it < ROWS/64; it++){
        int idx = threadIdx.x + it*256, row = idx >> 2, t = idx & 3;
        float4 v = *(const float4*)(G + (size_t)row*ld + 4*t);
        uint32_t* d = Ah + row*RP + t;
        d[0]=f2tf(v.x); d[4]=f2tf(v.y); d[8]=f2tf(v.z); d[12]=f2tf(v.w);
    }
}
template<int NC>     // transpose source: [16 k-rows][ld], NC n-cols
__device__ __forceinline__ void ldBt_hi(uint32_t* Bh, const float* G, int ld){
    #pragma unroll
    for (int it = 0; it < NC/64; it++){
        int idx = threadIdx.x + it*256;
        int kr = idx & 15, ng = idx >> 4;
        float4 v = *(const float4*)(G + (size_t)kr*ld + 4*ng);
        int p = (kr & 3)*4 + (kr >> 2);
        uint32_t* d = Bh + (4*ng)*RP + p;
        d[0]=f2tf(v.x); d[RP]=f2tf(v.y); d[2*RP]=f2tf(v.z); d[3*RP]=f2tf(v.w);
    }
}
__device__ __forceinline__ void fragA(uint32_t* a, const uint32_t* T, int row, int col){
    uint2 lo = *(const uint2*)(T + (size_t)row*RP + col);
    uint2 hi = *(const uint2*)(T + (size_t)(row+8)*RP + col);
    a[0]=lo.x; a[2]=lo.y; a[1]=hi.x; a[3]=hi.y;
}
__device__ __forceinline__ void fragB(uint32_t* b, const uint32_t* T, int row, int col){
    uint2 v = *(const uint2*)(T + (size_t)row*RP + col);
    b[0]=v.x; b[1]=v.y;
}
__device__ __forceinline__ void chunk_hi(float acc[2][4][4],
    const uint32_t* Ah, const uint32_t* Bh, int wm0, int wn0, int g, int c)
{
    #pragma unroll
    for (int s = 0; s < 2; s++){
        const int col = 4*c + 2*s;
        uint32_t ah[2][4], bh[4][2];
        #pragma unroll
        for (int mt = 0; mt < 2; mt++) fragA(ah[mt], Ah, wm0+mt*16+g, col);
        #pragma unroll
        for (int nt = 0; nt < 4; nt++) fragB(bh[nt], Bh, wn0+nt*8+g, col);
        #pragma unroll
        for (int mt = 0; mt < 2; mt++)
            #pragma unroll
            for (int nt = 0; nt < 4; nt++)
                mma8(acc[mt][nt], ah[mt], bh[nt]);
    }
}
#define PL_AH 0
#define PL_BH (128*RP)
#define PL_BUF (192*RP)      // words; 15360B per buf, x2 = 30720B

// ===========================================================================
// BF16 hi/lo split machinery with ldmatrix (Q/K proj, scores, PV).
// Row stride RB2=20 words (80B, 16B aligned) -> conflict-free ldmatrix.
// ===========================================================================
#define RB2 20

__device__ __forceinline__ void bsplit(float x, uint32_t& hb, uint32_t& lb){
    __nv_bfloat16 h = __float2bfloat16_rn(x);
    __nv_bfloat16 l = __float2bfloat16_rn(x - __bfloat162float(h));
    hb = (uint32_t)__bfloat16_as_ushort(h);
    lb = (uint32_t)__bfloat16_as_ushort(l);
}
__device__ __forceinline__ void mma16(float* c, const uint32_t* a, const uint32_t* b){
    asm volatile("mma.sync.aligned.m16n8k16.row.col.f32.bf16.bf16.f32 "
        "{%0,%1,%2,%3}, {%4,%5,%6,%7}, {%8,%9}, {%0,%1,%2,%3};"
        : "+f"(c[0]),"+f"(c[1]),"+f"(c[2]),"+f"(c[3])
        : "r"(a[0]),"r"(a[1]),"r"(a[2]),"r"(a[3]), "r"(b[0]),"r"(b[1]));
}
__device__ __forceinline__ void ldsm4(uint32_t* r, uint32_t a){
    asm volatile("ldmatrix.sync.aligned.m8n8.x4.shared.b16 {%0,%1,%2,%3}, [%4];"
        : "=r"(r[0]),"=r"(r[1]),"=r"(r[2]),"=r"(r[3]) : "r"(a));
}

template<int ROWS>
__device__ __forceinline__ void ldA_b2(uint32_t* Ah, uint32_t* Al, const float* G, int ld){
    #pragma unroll
    for (int it = 0; it < ROWS/32; it++){
        int idx = threadIdx.x + it*256;
        int row = idx >> 3, t = idx & 7;
        float4 v = *(const float4*)(G + (size_t)row*ld + 4*t);
        uint32_t hx,lx,hy,ly,hz,lz,hw,lw;
        bsplit(v.x,hx,lx); bsplit(v.y,hy,ly); bsplit(v.z,hz,lz); bsplit(v.w,hw,lw);
        uint2 hwd = make_uint2(hx | (hy<<16), hz | (hw<<16));
        uint2 lwd = make_uint2(lx | (ly<<16), lz | (lw<<16));
        *(uint2*)(Ah + (size_t)row*RB2 + 2*t) = hwd;
        *(uint2*)(Al + (size_t)row*RB2 + 2*t) = lwd;
    }
}
template<int NC>
__device__ __forceinline__ void ldBt_b2(uint32_t* Bh, uint32_t* Bl, const float* G, int ld){
    #pragma unroll
    for (int it = 0; it < NC/16; it++){
        int idx = threadIdx.x + it*256;
        int n = idx & (NC-1), wp = idx / NC;
        float a = G[(size_t)(2*wp)*ld + n];
        float b = G[(size_t)(2*wp+1)*ld + n];
        uint32_t ha,la,hb2,lb2;
        bsplit(a,ha,la); bsplit(b,hb2,lb2);
        Bh[(size_t)n*RB2 + wp] = ha | (hb2<<16);
        Bl[(size_t)n*RB2 + wp] = la | (lb2<<16);
    }
}

__device__ __forceinline__ void chunk_b2(float acc[2][4][4],
    uint32_t sAh, uint32_t sAl, uint32_t sBh, uint32_t sBl,
    int wm0, int wn0)
{
    const int L = threadIdx.x & 31;
    const int arow = (L & 7) + ((L >> 3) & 1) * 8;
    const int acol = (L >> 4) * 16;
    const int brow = (L & 7) + (L >> 4) * 8;
    const int bcol = ((L >> 3) & 1) * 16;

    #pragma unroll
    for (int s = 0; s < 2; s++){
        uint32_t ah[2][4], al[2][4], bbh[2][4], bbl[2][4];
        #pragma unroll
        for (int mt = 0; mt < 2; mt++){
            uint32_t off = (uint32_t)(wm0 + mt*16 + arow) * (RB2*4) + s*32 + acol;
            ldsm4(ah[mt], sAh + off);
            ldsm4(al[mt], sAl + off);
        }
        #pragma unroll
        for (int pr = 0; pr < 2; pr++){
            uint32_t off = (uint32_t)(wn0 + pr*16 + brow) * (RB2*4) + s*32 + bcol;
            ldsm4(bbh[pr], sBh + off);
            ldsm4(bbl[pr], sBl + off);
        }
        #pragma unroll
        for (int mt = 0; mt < 2; mt++)
            #pragma unroll
            for (int nt = 0; nt < 4; nt++){
                const uint32_t* bh_ = &bbh[nt>>1][(nt&1)*2];
                const uint32_t* bl_ = &bbl[nt>>1][(nt&1)*2];
                mma16(acc[mt][nt], al[mt], bh_);
                mma16(acc[mt][nt], ah[mt], bl_);
                mma16(acc[mt][nt], ah[mt], bh_);
            }
    }
}

#define B2_AH_B 0
#define B2_AL_B 10240        // 128*20*4
#define B2_BH_B 20480
#define B2_BL_B 25600        // + 64*20*4
#define B2_BUF_B 30720       // x2 buffers = 61440B

// ---------------------------------------------------------------------------
// Q/K projection (bf16 split): C = alpha*(A @ W + bias).  Block 128m x 64n,
// warp tile 32x32, double-buffered k32 chunks.
// ---------------------------------------------------------------------------
__global__ __launch_bounds__(256, 2) void gemm_b2(
    const float* __restrict__ A, const float* __restrict__ W,
    const float* __restrict__ bias, float* __restrict__ C, float alpha)
{
    extern __shared__ __align__(16) uint32_t sm[];
    const uint32_t sbase = (uint32_t)__cvta_generic_to_shared(sm);
    const int tid = threadIdx.x, wid = tid >> 5, lane = tid & 31;
    const int g = lane >> 2, c = lane & 3;
    const int wm0 = (wid >> 1) * 32, wn0 = (wid & 1) * 32;
    const int m0 = blockIdx.y * 128, n0 = blockIdx.x * 64;

    float acc[2][4][4] = {};

    auto load = [&](int buf, int k0){
        uint32_t* bw = sm + buf * (B2_BUF_B/4);
        ldA_b2<128>(bw + B2_AH_B/4, bw + B2_AL_B/4, A + (size_t)m0*F_ + k0, F_);
        ldBt_b2<64>(bw + B2_BH_B/4, bw + B2_BL_B/4, W + (size_t)k0*F_ + n0, F_);
    };

    load(0, 0);
    __syncthreads();
    for (int ch = 0; ch < 32; ch++){
        const int cur = ch & 1;
        if (ch + 1 < 32) load(cur ^ 1, (ch + 1) * 32);
        uint32_t sb = sbase + cur * B2_BUF_B;
        chunk_b2(acc, sb + B2_AH_B, sb + B2_AL_B, sb + B2_BH_B, sb + B2_BL_B, wm0, wn0);
        __syncthreads();
    }

    #pragma unroll
    for (int mt = 0; mt < 2; mt++){
        int m = m0 + wm0 + mt*16 + g;
        #pragma unroll
        for (int nt = 0; nt < 4; nt++){
            int n = n0 + wn0 + nt*8 + 2*c;
            float b0v = bias[n], b1v = bias[n+1];
            *(float2*)&C[(size_t)m*F_ + n] =
                make_float2(alpha*(acc[mt][nt][0]+b0v), alpha*(acc[mt][nt][1]+b1v));
            *(float2*)&C[(size_t)(m+8)*F_ + n] =
                make_float2(alpha*(acc[mt][nt][2]+b0v), alpha*(acc[mt][nt][3]+b1v));
        }
    }
}

// ---------------------------------------------------------------------------
// V / out projection (plain tf32): proven path.
// ---------------------------------------------------------------------------
__global__ __launch_bounds__(256, 2) void gemm_tf32(
    const float* __restrict__ A, const float* __restrict__ W,
    const float* __restrict__ bias, float* __restrict__ C, float alpha)
{
    extern __shared__ __align__(16) uint32_t sm[];
    const int tid = threadIdx.x, wid = tid >> 5, lane = tid & 31;
    const int g = lane >> 2, c = lane & 3;
    const int wm0 = (wid >> 1) * 32, wn0 = (wid & 1) * 32;
    const int m0 = blockIdx.y * 128, n0 = blockIdx.x * 64;

    float acc[2][4][4] = {};

    auto load = [&](int buf, int k0){
        uint32_t* b = sm + buf * PL_BUF;
        ldA_hi<128>(b + PL_AH, A + (size_t)m0*F_ + k0, F_);
        ldBt_hi<64>(b + PL_BH, W + (size_t)k0*F_ + n0, F_);
    };

    load(0, 0);
    __syncthreads();
    for (int ch = 0; ch < 64; ch++){
        const int cur = ch & 1;
        if (ch + 1 < 64) load(cur ^ 1, (ch + 1) * 16);
        uint32_t* b = sm + cur * PL_BUF;
        chunk_hi(acc, b + PL_AH, b + PL_BH, wm0, wn0, g, c);
        __syncthreads();
    }

    #pragma unroll
    for (int mt = 0; mt < 2; mt++){
        int m = m0 + wm0 + mt*16 + g;
        #pragma unroll
        for (int nt = 0; nt < 4; nt++){
            int n = n0 + wn0 + nt*8 + 2*c;
            float b0v = bias[n], b1v = bias[n+1];
            *(float2*)&C[(size_t)m*F_ + n] =
                make_float2(alpha*(acc[mt][nt][0]+b0v), alpha*(acc[mt][nt][1]+b1v));
            *(float2*)&C[(size_t)(m+8)*F_ + n] =
                make_float2(alpha*(acc[mt][nt][2]+b0v), alpha*(acc[mt][nt][3]+b1v));
        }
    }
}

// ---------------------------------------------------------------------------
// Scores (bf16 split + ldmatrix). Fully-masked tiles write zeros (these are
// the final attn values there — softmax no longer touches that region);
// causal tiles compute logits.
// ---------------------------------------------------------------------------
__global__ __launch_bounds__(256, 2) void scores_b2(float* __restrict__ attn)
{
    const int kt2 = blockIdx.x;           // 64-wide k tile, 0..31
    const int qt  = blockIdx.y;           // 128-wide q tile, 0..15
    const int bh = blockIdx.z;
    const int q0 = qt * 128, k0 = kt2 * 64;

    if (kt2 >= 2*(qt+1)){                 // fully-masked tile -> final zeros
        const int tid = threadIdx.x;
        const float4 z = make_float4(0.f, 0.f, 0.f, 0.f);
        #pragma unroll
        for (int it = 0; it < 8; it++){
            int idx = tid + it*256;       // 2048 float4 slots = 128x64
            int row = idx >> 4, c4 = (idx & 15) * 4;
            *(float4*)&attn[((size_t)bh*S_ + q0 + row)*S_ + k0 + c4] = z;
        }
        return;
    }

    const int b = bh >> 4, h = bh & 15;
    const float* Qb = g_q + ((size_t)b*S_*H_ + h)*D_;
    const float* Kb = g_k + ((size_t)b*S_*H_ + h)*D_;

    extern __shared__ __align__(16) uint32_t sm[];
    const uint32_t sbase = (uint32_t)__cvta_generic_to_shared(sm);
    const int tid = threadIdx.x, wid = tid >> 5, lane = tid & 31;
    const int g = lane >> 2, c = lane & 3;
    const int wm0 = (wid >> 1) * 32, wn0 = (wid & 1) * 32;

    float acc[2][4][4] = {};

    auto load = [&](int buf, int d0){
        uint32_t* bw = sm + buf * (B2_BUF_B/4);
        ldA_b2<128>(bw + B2_AH_B/4, bw + B2_AL_B/4, Qb + (size_t)q0*HD + d0, HD);
        ldA_b2<64> (bw + B2_BH_B/4, bw + B2_BL_B/4, Kb + (size_t)k0*HD + d0, HD);
    };

    load(0, 0);
    __syncthreads();
    for (int ch = 0; ch < 2; ch++){
        const int cur = ch & 1;
        if (ch + 1 < 2) load(cur ^ 1, (ch + 1) * 32);
        uint32_t sb = sbase + cur * B2_BUF_B;
        chunk_b2(acc, sb + B2_AH_B, sb + B2_AL_B, sb + B2_BH_B, sb + B2_BL_B, wm0, wn0);
        __syncthreads();
    }

    #pragma unroll
    for (int mt = 0; mt < 2; mt++){
        int q = q0 + wm0 + mt*16 + g;
        float* r0 = attn + ((size_t)bh*S_ + q)*S_;
        float* r1 = attn + ((size_t)bh*S_ + q + 8)*S_;
        #pragma unroll
        for (int nt = 0; nt < 4; nt++){
            int n = k0 + wn0 + nt*8 + 2*c;
            *(float2*)&r0[n] = make_float2(acc[mt][nt][0], acc[mt][nt][1]);
            *(float2*)&r1[n] = make_float2(acc[mt][nt][2], acc[mt][nt][3]);
        }
    }
}

// ---------------------------------------------------------------------------
// Causal softmax in-place. Reads only the causal region; writes only
// k < klim = (qt+1)*128 (the q-tile's k-extent; beyond that scores already
// wrote final zeros). Masked entries within klim -> exact 0.
// ---------------------------------------------------------------------------
__global__ __launch_bounds__(256) void softmax_kernel(float* __restrict__ attn)
{
    const int row = blockIdx.x;
    const int q = row % S_;
    float* p = attn + (size_t)row * S_;
    const int len = q + 1;
    const int klim = ((q >> 7) + 1) << 7;   // (qt+1)*128
    const int tid = threadIdx.x;
    const int lane = tid & 31, warp = tid >> 5;

    __shared__ float sred[8];
    __shared__ float sbc[2];

    float4 v[2];
    float mx = -INFINITY;
    #pragma unroll
    for (int i = 0; i < 2; i++){
        int b0 = 4*(tid + i*256);
        float4 u = make_float4(-INFINITY, -INFINITY, -INFINITY, -INFINITY);
        if (b0 < len){
            u = *(const float4*)(p + b0);
            u.x = (b0+0 < len) ? u.x : -INFINITY;
            u.y = (b0+1 < len) ? u.y : -INFINITY;
            u.z = (b0+2 < len) ? u.z : -INFINITY;
            u.w = (b0+3 < len) ? u.w : -INFINITY;
        }
        v[i] = u;
        mx = fmaxf(mx, fmaxf(fmaxf(u.x, u.y), fmaxf(u.z, u.w)));
    }
    #pragma unroll
    for (int o = 16; o > 0; o >>= 1) mx = fmaxf(mx, __shfl_xor_sync(0xffffffffu, mx, o));
    if (lane == 0) sred[warp] = mx;
    __syncthreads();
    if (tid == 0){
        float m = sred[0];
        #pragma unroll
        for (int i = 1; i < 8; i++) m = fmaxf(m, sred[i]);
        sbc[0] = m;
    }
    __syncthreads();
    mx = sbc[0];

    float s = 0.f;
    #pragma unroll
    for (int i = 0; i < 2; i++){
        int b0 = 4*(tid + i*256);
        float4 u = v[i];
        if (b0 < len){
            u.x = (b0+0 < len) ? __expf(u.x - mx) : 0.f;
            u.y = (b0+1 < len) ? __expf(u.y - mx) : 0.f;
            u.z = (b0+2 < len) ? __expf(u.z - mx) : 0.f;
            u.w = (b0+3 < len) ? __expf(u.w - mx) : 0.f;
            s += (u.x + u.y) + (u.z + u.w);
        } else {
            u = make_float4(0.f, 0.f, 0.f, 0.f);
        }
        v[i] = u;
    }
    #pragma unroll
    for (int o = 16; o > 0; o >>= 1) s += __shfl_xor_sync(0xffffffffu, s, o);
    if (lane == 0) sred[warp] = s;
    __syncthreads();
    if (tid == 0){
        float t = 0.f;
        #pragma unroll
        for (int i = 0; i < 8; i++) t += sred[i];
        sbc[1] = t;
    }
    __syncthreads();
    const float inv = 1.0f / sbc[1];

    #pragma unroll
    for (int i = 0; i < 2; i++){
        int b0 = 4*(tid + i*256);
        if (b0 < klim){
            float4 u = v[i];
            u.x *= inv; u.y *= inv; u.z *= inv; u.w *= inv;
            *(float4*)(p + b0) = u;
        }
    }
}

// ---------------------------------------------------------------------------
// PV (bf16 hi/lo split): x[q][d] = sum_k P[q][k] * V[k][d].  Block 128q x 64d,
// triangle pairing (qt, 15-qt), double-buffered k32 chunks.
// ---------------------------------------------------------------------------
__device__ __forceinline__ void pv_tile(
    const float* __restrict__ attn, const float* __restrict__ Vb,
    float* __restrict__ Xb, int bh, int qt, uint32_t* sm, uint32_t sbase)
{
    const int tid = threadIdx.x, wid = tid >> 5, lane = tid & 31;
    const int g = lane >> 2, c = lane & 3;
    const int wm0 = (wid >> 1) * 32, wn0 = (wid & 1) * 32;
    const int q0 = qt * 128;
    const int NCH = (qt + 1) * 4;        // 32-wide k chunks up to causal bound

    float acc[2][4][4] = {};

    auto load = [&](int buf, int k0){
        uint32_t* bw = sm + buf * (B2_BUF_B/4);
        ldA_b2<128>(bw + B2_AH_B/4, bw + B2_AL_B/4,
                    attn + ((size_t)bh*S_ + q0)*S_ + k0, S_);
        ldBt_b2<64>(bw + B2_BH_B/4, bw + B2_BL_B/4, Vb + (size_t)k0*HD, HD);
    };

    load(0, 0);
    __syncthreads();
    for (int ch = 0; ch < NCH; ch++){
        const int cur = ch & 1;
        if (ch + 1 < NCH) load(cur ^ 1, (ch + 1) * 32);
        uint32_t sb = sbase + cur * B2_BUF_B;
        chunk_b2(acc, sb + B2_AH_B, sb + B2_AL_B, sb + B2_BH_B, sb + B2_BL_B, wm0, wn0);
        __syncthreads();
    }

    #pragma unroll
    for (int mt = 0; mt < 2; mt++){
        int q = q0 + wm0 + mt*16 + g;
        #pragma unroll
        for (int nt = 0; nt < 4; nt++){
            int n = wn0 + nt*8 + 2*c;
            *(float2*)&Xb[(size_t)q*HD + n] =
                make_float2(acc[mt][nt][0], acc[mt][nt][1]);
            *(float2*)&Xb[(size_t)(q+8)*HD + n] =
                make_float2(acc[mt][nt][2], acc[mt][nt][3]);
        }
    }
}

__global__ __launch_bounds__(256, 2) void pv_mma(const float* __restrict__ attn)
{
    extern __shared__ __align__(16) uint32_t sm[];
    const uint32_t sbase = (uint32_t)__cvta_generic_to_shared(sm);
    const int pair = blockIdx.x;          // 0..7
    const int bh = blockIdx.y;
    const int b = bh >> 4, h = bh & 15;
    const float* Vb = g_v + ((size_t)b*S_*H_ + h)*D_;
    float* Xb = g_x + ((size_t)b*S_*H_ + h)*D_;

    pv_tile(attn, Vb, Xb, bh, pair, sm, sbase);
    __syncthreads();
    pv_tile(attn, Vb, Xb, bh, 15 - pair, sm, sbase);
}

// ---------------------------------------------------------------------------
// Launch
// ---------------------------------------------------------------------------
extern "C" void kernel_launch(void* const* d_in, const int* in_sizes, int n_in,
                              void* d_out, int out_size)
{
    const float* inputs_q  = (const float*)d_in[0];
    const float* inputs_kv = (const float*)d_in[1];
    // d_in[2] = mask (known causal, unused)
    const float* Wq = (const float*)d_in[3];
    const float* bq = (const float*)d_in[4];
    const float* Wk = (const float*)d_in[5];
    const float* bk = (const float*)d_in[6];
    const float* Wv = (const float*)d_in[7];
    const float* bv = (const float*)d_in[8];
    const float* Wo = (const float*)d_in[9];
    const float* bo = (const float*)d_in[10];

    float* out  = (float*)d_out;                       // [B,S,F]
    float* attn = out + (size_t)MTOK * F_;             // [B,H,S,S]

    float* gq; cudaGetSymbolAddress((void**)&gq, g_q);
    float* gk; cudaGetSymbolAddress((void**)&gk, g_k);
    float* gv; cudaGetSymbolAddress((void**)&gv, g_v);
    float* gx; cudaGetSymbolAddress((void**)&gx, g_x);

    const int SM_B2 = 2 * B2_BUF_B;     // 61440 bytes
    const int SM_PL = 2 * PL_BUF * 4;   // 30720 bytes
    cudaFuncSetAttribute(gemm_b2,   cudaFuncAttributeMaxDynamicSharedMemorySize, SM_B2);
    cudaFuncSetAttribute(scores_b2, cudaFuncAttributeMaxDynamicSharedMemorySize, SM_B2);
    cudaFuncSetAttribute(gemm_tf32, cudaFuncAttributeMaxDynamicSharedMemorySize, SM_PL);
    cudaFuncSetAttribute(pv_mma,    cudaFuncAttributeMaxDynamicSharedMemorySize, SM_B2);

    dim3 gproj(F_ / 64, MTOK / 128);    // (16, 32)
    const float qscale = 0.125f;        // 1/sqrt(Dh)

    // Q/K projections in bf16 hi/lo split (protect softmax logits); V plain tf32.
    gemm_b2<<<gproj, 256, SM_B2>>>(inputs_q,  Wq, bq, gq, qscale);
    gemm_b2<<<gproj, 256, SM_B2>>>(inputs_kv, Wk, bk, gk, 1.0f);
    gemm_tf32<<<gproj, 256, SM_PL>>>(inputs_kv, Wv, bv, gv, 1.0f);

    dim3 gsc(2 * S_ / 128, S_ / 128, B_ * H_);  // (32, 16, 32): causal + zero tiles
    scores_b2<<<gsc, 256, SM_B2>>>(attn);

    softmax_kernel<<<B_ * H_ * S_, 256>>>(attn);

    dim3 gpv(S_ / 256, B_ * H_);                // (8, 32) triangle pairs
    pv_mma<<<gpv, 256, SM_B2>>>(attn);

    gemm_tf32<<<gproj, 256, SM_PL>>>(gx, Wo, bo, out, 1.0f);
}

// round 16
// speedup vs baseline: 1.5696x; 1.1404x over previous
#include <cuda_runtime.h>
#include <cuda_bf16.h>
#include <math.h>
#include <stdint.h>

// Problem constants
#define B_  2
#define S_  2048
#define F_  1024
#define H_  16
#define D_  64
#define MTOK (B_*S_)     // 4096 tokens
#define HD   (H_*D_)     // 1024

// Device scratch (no cudaMalloc allowed)
__device__ float g_q[MTOK*HD];
__device__ float g_k[MTOK*HD];
__device__ float g_v[MTOK*HD];
__device__ float g_x[MTOK*HD];

// ===========================================================================
// BF16 hi/lo split machinery with ldmatrix (all GEMM kernels).
// Row stride RB2=20 words (80B, 16B aligned) -> conflict-free ldmatrix.
// ===========================================================================
#define RB2 20

__device__ __forceinline__ void bsplit(float x, uint32_t& hb, uint32_t& lb){
    __nv_bfloat16 h = __float2bfloat16_rn(x);
    __nv_bfloat16 l = __float2bfloat16_rn(x - __bfloat162float(h));
    hb = (uint32_t)__bfloat16_as_ushort(h);
    lb = (uint32_t)__bfloat16_as_ushort(l);
}
__device__ __forceinline__ void mma16(float* c, const uint32_t* a, const uint32_t* b){
    asm volatile("mma.sync.aligned.m16n8k16.row.col.f32.bf16.bf16.f32 "
        "{%0,%1,%2,%3}, {%4,%5,%6,%7}, {%8,%9}, {%0,%1,%2,%3};"
        : "+f"(c[0]),"+f"(c[1]),"+f"(c[2]),"+f"(c[3])
        : "r"(a[0]),"r"(a[1]),"r"(a[2]),"r"(a[3]), "r"(b[0]),"r"(b[1]));
}
__device__ __forceinline__ void ldsm4(uint32_t* r, uint32_t a){
    asm volatile("ldmatrix.sync.aligned.m8n8.x4.shared.b16 {%0,%1,%2,%3}, [%4];"
        : "=r"(r[0]),"=r"(r[1]),"=r"(r[2]),"=r"(r[3]) : "r"(a));
}

// Row-major source [ROWS][ld] fp32, 32 k-cols -> hi/lo packed bf16 tiles.
template<int ROWS>
__device__ __forceinline__ void ldA_b2(uint32_t* Ah, uint32_t* Al, const float* G, int ld){
    #pragma unroll
    for (int it = 0; it < ROWS/32; it++){
        int idx = threadIdx.x + it*256;
        int row = idx >> 3, t = idx & 7;
        float4 v = *(const float4*)(G + (size_t)row*ld + 4*t);
        uint32_t hx,lx,hy,ly,hz,lz,hw,lw;
        bsplit(v.x,hx,lx); bsplit(v.y,hy,ly); bsplit(v.z,hz,lz); bsplit(v.w,hw,lw);
        uint2 hwd = make_uint2(hx | (hy<<16), hz | (hw<<16));
        uint2 lwd = make_uint2(lx | (ly<<16), lz | (lw<<16));
        *(uint2*)(Ah + (size_t)row*RB2 + 2*t) = hwd;
        *(uint2*)(Al + (size_t)row*RB2 + 2*t) = lwd;
    }
}
// Transpose source: [32 k-rows][ld] fp32, NC n-cols -> row-major [n][k] tiles.
template<int NC>
__device__ __forceinline__ void ldBt_b2(uint32_t* Bh, uint32_t* Bl, const float* G, int ld){
    #pragma unroll
    for (int it = 0; it < NC/16; it++){
        int idx = threadIdx.x + it*256;
        int n = idx & (NC-1), wp = idx / NC;
        float a = G[(size_t)(2*wp)*ld + n];
        float b = G[(size_t)(2*wp+1)*ld + n];
        uint32_t ha,la,hb2,lb2;
        bsplit(a,ha,la); bsplit(b,hb2,lb2);
        Bh[(size_t)n*RB2 + wp] = ha | (hb2<<16);
        Bl[(size_t)n*RB2 + wp] = la | (lb2<<16);
    }
}

// One 32-deep chunk via ldmatrix: acc += A(128 rows)*B^T(64 rows), warp tile 32x32.
__device__ __forceinline__ void chunk_b2(float acc[2][4][4],
    uint32_t sAh, uint32_t sAl, uint32_t sBh, uint32_t sBl,
    int wm0, int wn0)
{
    const int L = threadIdx.x & 31;
    const int arow = (L & 7) + ((L >> 3) & 1) * 8;
    const int acol = (L >> 4) * 16;
    const int brow = (L & 7) + (L >> 4) * 8;
    const int bcol = ((L >> 3) & 1) * 16;

    #pragma unroll
    for (int s = 0; s < 2; s++){
        uint32_t ah[2][4], al[2][4], bbh[2][4], bbl[2][4];
        #pragma unroll
        for (int mt = 0; mt < 2; mt++){
            uint32_t off = (uint32_t)(wm0 + mt*16 + arow) * (RB2*4) + s*32 + acol;
            ldsm4(ah[mt], sAh + off);
            ldsm4(al[mt], sAl + off);
        }
        #pragma unroll
        for (int pr = 0; pr < 2; pr++){
            uint32_t off = (uint32_t)(wn0 + pr*16 + brow) * (RB2*4) + s*32 + bcol;
            ldsm4(bbh[pr], sBh + off);
            ldsm4(bbl[pr], sBl + off);
        }
        #pragma unroll
        for (int mt = 0; mt < 2; mt++)
            #pragma unroll
            for (int nt = 0; nt < 4; nt++){
                const uint32_t* bh_ = &bbh[nt>>1][(nt&1)*2];
                const uint32_t* bl_ = &bbl[nt>>1][(nt&1)*2];
                mma16(acc[mt][nt], al[mt], bh_);
                mma16(acc[mt][nt], ah[mt], bl_);
                mma16(acc[mt][nt], ah[mt], bh_);
            }
    }
}

#define B2_AH_B 0
#define B2_AL_B 10240        // 128*20*4
#define B2_BH_B 20480
#define B2_BL_B 25600        // + 64*20*4
#define B2_BUF_B 30720       // x2 buffers = 61440B

// ---------------------------------------------------------------------------
// Projection GEMM (bf16 split): C = alpha*(A[4096][1024] @ W[1024][1024] + bias)
// Block 128m x 64n, warp tile 32x32, double-buffered k32 chunks.
// ---------------------------------------------------------------------------
__global__ __launch_bounds__(256, 2) void gemm_b2(
    const float* __restrict__ A, const float* __restrict__ W,
    const float* __restrict__ bias, float* __restrict__ C, float alpha)
{
    extern __shared__ __align__(16) uint32_t sm[];
    const uint32_t sbase = (uint32_t)__cvta_generic_to_shared(sm);
    const int tid = threadIdx.x, wid = tid >> 5, lane = tid & 31;
    const int g = lane >> 2, c = lane & 3;
    const int wm0 = (wid >> 1) * 32, wn0 = (wid & 1) * 32;
    const int m0 = blockIdx.y * 128, n0 = blockIdx.x * 64;

    float acc[2][4][4] = {};

    auto load = [&](int buf, int k0){
        uint32_t* bw = sm + buf * (B2_BUF_B/4);
        ldA_b2<128>(bw + B2_AH_B/4, bw + B2_AL_B/4, A + (size_t)m0*F_ + k0, F_);
        ldBt_b2<64>(bw + B2_BH_B/4, bw + B2_BL_B/4, W + (size_t)k0*F_ + n0, F_);
    };

    load(0, 0);
    __syncthreads();
    for (int ch = 0; ch < 32; ch++){
        const int cur = ch & 1;
        if (ch + 1 < 32) load(cur ^ 1, (ch + 1) * 32);
        uint32_t sb = sbase + cur * B2_BUF_B;
        chunk_b2(acc, sb + B2_AH_B, sb + B2_AL_B, sb + B2_BH_B, sb + B2_BL_B, wm0, wn0);
        __syncthreads();
    }

    #pragma unroll
    for (int mt = 0; mt < 2; mt++){
        int m = m0 + wm0 + mt*16 + g;
        #pragma unroll
        for (int nt = 0; nt < 4; nt++){
            int n = n0 + wn0 + nt*8 + 2*c;
            float b0v = bias[n], b1v = bias[n+1];
            *(float2*)&C[(size_t)m*F_ + n] =
                make_float2(alpha*(acc[mt][nt][0]+b0v), alpha*(acc[mt][nt][1]+b1v));
            *(float2*)&C[(size_t)(m+8)*F_ + n] =
                make_float2(alpha*(acc[mt][nt][2]+b0v), alpha*(acc[mt][nt][3]+b1v));
        }
    }
}

// ---------------------------------------------------------------------------
// Scores, Q-resident: one block per (pair, bh); processes qt = pair and
// 15-pair. Q tile (128q x 64d, hi/lo) loaded+split ONCE per qt into resident
// smem; K tiles (64k x 64d) streamed double-buffered over the causal range;
// fully-masked tiles zero-filled in the same block.
// Per pair: 34 causal k-tiles + 30 zero tiles -> uniform work.
//
// Smem (words): Q hi ch0 @0, ch1 @2560; Q lo ch0 @5120, ch1 @7680;
// K buf b @10240+b*5120: hi ch0 +0, ch1 +1280; lo ch0 +2560, ch1 +3840.
// Total 20480 words = 81920 B.
// ---------------------------------------------------------------------------
#define SC_Q_H(ch)      ((ch)*2560)
#define SC_Q_L(ch)      (5120 + (ch)*2560)
#define SC_K_BASE(b)    (10240 + (b)*5120)
#define SC_SMEM_B       81920

__global__ __launch_bounds__(256, 2) void scores_qres(float* __restrict__ attn)
{
    const int pair = blockIdx.x;          // 0..7
    const int bh = blockIdx.y;            // 0..31
    const int b = bh >> 4, h = bh & 15;
    const float* Qb = g_q + ((size_t)b*S_*H_ + h)*D_;
    const float* Kb = g_k + ((size_t)b*S_*H_ + h)*D_;

    extern __shared__ __align__(16) uint32_t sm[];
    const uint32_t sbase = (uint32_t)__cvta_generic_to_shared(sm);
    const int tid = threadIdx.x, wid = tid >> 5, lane = tid & 31;
    const int g = lane >> 2, c = lane & 3;
    const int wm0 = (wid >> 1) * 32, wn0 = (wid & 1) * 32;

    #pragma unroll
    for (int half = 0; half < 2; half++){
        const int qt = half ? (15 - pair) : pair;
        const int q0 = qt * 128;
        const int ncaus = 2*(qt + 1);     // causal 64-wide k tiles

        // Load Q (both 32-d chunks, hi+lo). Previous iteration ended with a
        // __syncthreads() after its last compute, so Q smem is free.
        ldA_b2<128>(sm + SC_Q_H(0), sm + SC_Q_L(0), Qb + (size_t)q0*HD + 0,  HD);
        ldA_b2<128>(sm + SC_Q_H(1), sm + SC_Q_L(1), Qb + (size_t)q0*HD + 32, HD);

        auto loadK = [&](int buf, int k0){
            uint32_t* kb = sm + SC_K_BASE(buf);
            ldA_b2<64>(kb + 0,    kb + 2560, Kb + (size_t)k0*HD + 0,  HD);
            ldA_b2<64>(kb + 1280, kb + 3840, Kb + (size_t)k0*HD + 32, HD);
        };

        loadK(0, 0);
        __syncthreads();

        for (int kt2 = 0; kt2 < ncaus; kt2++){
            const int cur = kt2 & 1;
            if (kt2 + 1 < ncaus) loadK(cur ^ 1, (kt2 + 1) * 64);

            float acc[2][4][4] = {};
            const uint32_t qB = sbase;
            const uint32_t kB = sbase + SC_K_BASE(cur)*4;
            chunk_b2(acc, qB + SC_Q_H(0)*4, qB + SC_Q_L(0)*4,
                          kB + 0,           kB + 2560*4, wm0, wn0);
            chunk_b2(acc, qB + SC_Q_H(1)*4, qB + SC_Q_L(1)*4,
                          kB + 1280*4,      kB + 3840*4, wm0, wn0);
            __syncthreads();

            const int k0 = kt2 * 64;
            #pragma unroll
            for (int mt = 0; mt < 2; mt++){
                int q = q0 + wm0 + mt*16 + g;
                float* r0 = attn + ((size_t)bh*S_ + q)*S_;
                float* r1 = attn + ((size_t)bh*S_ + q + 8)*S_;
                #pragma unroll
                for (int nt = 0; nt < 4; nt++){
                    int n = k0 + wn0 + nt*8 + 2*c;
                    *(float2*)&r0[n] = make_float2(acc[mt][nt][0], acc[mt][nt][1]);
                    *(float2*)&r1[n] = make_float2(acc[mt][nt][2], acc[mt][nt][3]);
                }
            }
        }

        // Fully-masked tiles: final zeros (softmax never touches this region).
        const float4 z = make_float4(0.f, 0.f, 0.f, 0.f);
        for (int kt2 = ncaus; kt2 < 32; kt2++){
            const int k0 = kt2 * 64;
            #pragma unroll
            for (int it = 0; it < 8; it++){
                int idx = tid + it*256;   // 2048 float4 slots = 128x64
                int row = idx >> 4, c4 = (idx & 15) * 4;
                *(float4*)&attn[((size_t)bh*S_ + q0 + row)*S_ + k0 + c4] = z;
            }
        }
    }
}

// ---------------------------------------------------------------------------
// Causal softmax in-place. Reads only the causal region; writes only
// k < klim = (qt+1)*128 (scores wrote final zeros beyond). Masked entries
// within klim -> exact 0.
// ---------------------------------------------------------------------------
__global__ __launch_bounds__(256) void softmax_kernel(float* __restrict__ attn)
{
    const int row = blockIdx.x;
    const int q = row % S_;
    float* p = attn + (size_t)row * S_;
    const int len = q + 1;
    const int klim = ((q >> 7) + 1) << 7;   // (qt+1)*128
    const int tid = threadIdx.x;
    const int lane = tid & 31, warp = tid >> 5;

    __shared__ float sred[8];
    __shared__ float sbc[2];

    float4 v[2];
    float mx = -INFINITY;
    #pragma unroll
    for (int i = 0; i < 2; i++){
        int b0 = 4*(tid + i*256);
        float4 u = make_float4(-INFINITY, -INFINITY, -INFINITY, -INFINITY);
        if (b0 < len){
            u = *(const float4*)(p + b0);
            u.x = (b0+0 < len) ? u.x : -INFINITY;
            u.y = (b0+1 < len) ? u.y : -INFINITY;
            u.z = (b0+2 < len) ? u.z : -INFINITY;
            u.w = (b0+3 < len) ? u.w : -INFINITY;
        }
        v[i] = u;
        mx = fmaxf(mx, fmaxf(fmaxf(u.x, u.y), fmaxf(u.z, u.w)));
    }
    #pragma unroll
    for (int o = 16; o > 0; o >>= 1) mx = fmaxf(mx, __shfl_xor_sync(0xffffffffu, mx, o));
    if (lane == 0) sred[warp] = mx;
    __syncthreads();
    if (tid == 0){
        float m = sred[0];
        #pragma unroll
        for (int i = 1; i < 8; i++) m = fmaxf(m, sred[i]);
        sbc[0] = m;
    }
    __syncthreads();
    mx = sbc[0];

    float s = 0.f;
    #pragma unroll
    for (int i = 0; i < 2; i++){
        int b0 = 4*(tid + i*256);
        float4 u = v[i];
        if (b0 < len){
            u.x = (b0+0 < len) ? __expf(u.x - mx) : 0.f;
            u.y = (b0+1 < len) ? __expf(u.y - mx) : 0.f;
            u.z = (b0+2 < len) ? __expf(u.z - mx) : 0.f;
            u.w = (b0+3 < len) ? __expf(u.w - mx) : 0.f;
            s += (u.x + u.y) + (u.z + u.w);
        } else {
            u = make_float4(0.f, 0.f, 0.f, 0.f);
        }
        v[i] = u;
    }
    #pragma unroll
    for (int o = 16; o > 0; o >>= 1) s += __shfl_xor_sync(0xffffffffu, s, o);
    if (lane == 0) sred[warp] = s;
    __syncthreads();
    if (tid == 0){
        float t = 0.f;
        #pragma unroll
        for (int i = 0; i < 8; i++) t += sred[i];
        sbc[1] = t;
    }
    __syncthreads();
    const float inv = 1.0f / sbc[1];

    #pragma unroll
    for (int i = 0; i < 2; i++){
        int b0 = 4*(tid + i*256);
        if (b0 < klim){
            float4 u = v[i];
            u.x *= inv; u.y *= inv; u.z *= inv; u.w *= inv;
            *(float4*)(p + b0) = u;
        }
    }
}

// ---------------------------------------------------------------------------
// PV (bf16 hi/lo split): x[q][d] = sum_k P[q][k] * V[k][d].  Block 128q x 64d,
// triangle pairing (qt, 15-qt), double-buffered k32 chunks.
// ---------------------------------------------------------------------------
__device__ __forceinline__ void pv_tile(
    const float* __restrict__ attn, const float* __restrict__ Vb,
    float* __restrict__ Xb, int bh, int qt, uint32_t* sm, uint32_t sbase)
{
    const int tid = threadIdx.x, wid = tid >> 5, lane = tid & 31;
    const int g = lane >> 2, c = lane & 3;
    const int wm0 = (wid >> 1) * 32, wn0 = (wid & 1) * 32;
    const int q0 = qt * 128;
    const int NCH = (qt + 1) * 4;        // 32-wide k chunks up to causal bound

    float acc[2][4][4] = {};

    auto load = [&](int buf, int k0){
        uint32_t* bw = sm + buf * (B2_BUF_B/4);
        ldA_b2<128>(bw + B2_AH_B/4, bw + B2_AL_B/4,
                    attn + ((size_t)bh*S_ + q0)*S_ + k0, S_);
        ldBt_b2<64>(bw + B2_BH_B/4, bw + B2_BL_B/4, Vb + (size_t)k0*HD, HD);
    };

    load(0, 0);
    __syncthreads();
    for (int ch = 0; ch < NCH; ch++){
        const int cur = ch & 1;
        if (ch + 1 < NCH) load(cur ^ 1, (ch + 1) * 32);
        uint32_t sb = sbase + cur * B2_BUF_B;
        chunk_b2(acc, sb + B2_AH_B, sb + B2_AL_B, sb + B2_BH_B, sb + B2_BL_B, wm0, wn0);
        __syncthreads();
    }

    #pragma unroll
    for (int mt = 0; mt < 2; mt++){
        int q = q0 + wm0 + mt*16 + g;
        #pragma unroll
        for (int nt = 0; nt < 4; nt++){
            int n = wn0 + nt*8 + 2*c;
            *(float2*)&Xb[(size_t)q*HD + n] =
                make_float2(acc[mt][nt][0], acc[mt][nt][1]);
            *(float2*)&Xb[(size_t)(q+8)*HD + n] =
                make_float2(acc[mt][nt][2], acc[mt][nt][3]);
        }
    }
}

__global__ __launch_bounds__(256, 2) void pv_mma(const float* __restrict__ attn)
{
    extern __shared__ __align__(16) uint32_t sm[];
    const uint32_t sbase = (uint32_t)__cvta_generic_to_shared(sm);
    const int pair = blockIdx.x;          // 0..7
    const int bh = blockIdx.y;
    const int b = bh >> 4, h = bh & 15;
    const float* Vb = g_v + ((size_t)b*S_*H_ + h)*D_;
    float* Xb = g_x + ((size_t)b*S_*H_ + h)*D_;

    pv_tile(attn, Vb, Xb, bh, pair, sm, sbase);
    __syncthreads();
    pv_tile(attn, Vb, Xb, bh, 15 - pair, sm, sbase);
}

// ---------------------------------------------------------------------------
// Launch
// ---------------------------------------------------------------------------
extern "C" void kernel_launch(void* const* d_in, const int* in_sizes, int n_in,
                              void* d_out, int out_size)
{
    const float* inputs_q  = (const float*)d_in[0];
    const float* inputs_kv = (const float*)d_in[1];
    // d_in[2] = mask (known causal, unused)
    const float* Wq = (const float*)d_in[3];
    const float* bq = (const float*)d_in[4];
    const float* Wk = (const float*)d_in[5];
    const float* bk = (const float*)d_in[6];
    const float* Wv = (const float*)d_in[7];
    const float* bv = (const float*)d_in[8];
    const float* Wo = (const float*)d_in[9];
    const float* bo = (const float*)d_in[10];

    float* out  = (float*)d_out;                       // [B,S,F]
    float* attn = out + (size_t)MTOK * F_;             // [B,H,S,S]

    float* gq; cudaGetSymbolAddress((void**)&gq, g_q);
    float* gk; cudaGetSymbolAddress((void**)&gk, g_k);
    float* gv; cudaGetSymbolAddress((void**)&gv, g_v);
    float* gx; cudaGetSymbolAddress((void**)&gx, g_x);

    const int SM_B2 = 2 * B2_BUF_B;     // 61440 bytes
    cudaFuncSetAttribute(gemm_b2,     cudaFuncAttributeMaxDynamicSharedMemorySize, SM_B2);
    cudaFuncSetAttribute(scores_qres, cudaFuncAttributeMaxDynamicSharedMemorySize, SC_SMEM_B);
    cudaFuncSetAttribute(pv_mma,      cudaFuncAttributeMaxDynamicSharedMemorySize, SM_B2);

    dim3 gproj(F_ / 64, MTOK / 128);    // (16, 32)
    const float qscale = 0.125f;        // 1/sqrt(Dh)

    // All projections in bf16 hi/lo split.
    gemm_b2<<<gproj, 256, SM_B2>>>(inputs_q,  Wq, bq, gq, qscale);
    gemm_b2<<<gproj, 256, SM_B2>>>(inputs_kv, Wk, bk, gk, 1.0f);
    gemm_b2<<<gproj, 256, SM_B2>>>(inputs_kv, Wv, bv, gv, 1.0f);

    dim3 gsc(8, B_ * H_);               // (8 pairs, 32 bh): Q-resident scores
    scores_qres<<<gsc, 256, SC_SMEM_B>>>(attn);

    softmax_kernel<<<B_ * H_ * S_, 256>>>(attn);

    dim3 gpv(S_ / 256, B_ * H_);        // (8, 32) triangle pairs
    pv_mma<<<gpv, 256, SM_B2>>>(attn);

    gemm_b2<<<gproj, 256, SM_B2>>>(gx, Wo, bo, out, 1.0f);
}